// round 12
// baseline (speedup 1.0000x reference)
#include <cuda_runtime.h>

// NVAR feature expansion.  X: (8,4,4096) f32 -> out: (8,4,3996,231) f32
//   out[p, 0]      = 1
//   out[p, 1+k]    = lin[k] = X[br, t + 82 + 2k]
//   out[p, 11+m]   = lin[a]*lin[b]*lin[c], lex triples a<=b<=c over 0..9
//
// R11 = R4 (best bench: STS stage + float4 STG copy) + the missing
// occupancy fix: max shared-memory carveout so 7 CTAs/SM fit (R4 was
// silently capped at 3 CTAs/SM by the default ~100KB carveout), giving
// ~2.3x the store MLP. Copy loop unrolled for more stores in flight.

constexpr int K_TAPS   = 10;
constexpr int NF       = 231;
constexpr int N_TIME   = 4096;
constexpr int T_OUT    = 3996;
constexpr int BASE_OFF = 82;           // TRANSIENTS - (K-1)*SKIP
constexpr int SKIP     = 2;

constexpr int NP_BLK   = 32;                        // points per CTA
constexpr int NTHREADS = 128;
constexpr int NSEG     = 4;
constexpr int FL_BLK   = NP_BLK * NF;               // 7392 floats (div by 4)
constexpr int V4_BLK   = FL_BLK / 4;                // 1848 float4
constexpr int GRID     = (8 * 4 * T_OUT) / NP_BLK;  // 3996 exactly
constexpr int SMEM_B   = FL_BLK * 4;                // 29568 bytes

__device__ constexpr int SEG_LO[NSEG + 1] = {0, 58, 116, 174, 231};

__global__ __launch_bounds__(NTHREADS) void nvar_kernel(const float* __restrict__ X,
                                                        float* __restrict__ out) {
    extern __shared__ __align__(16) float s_feat[];  // point-major, stride NF

    const int tid = threadIdx.x;
    const int q   = tid >> 5;                       // warp = feature segment
    const int lp  = tid & 31;                       // lane = local point
    const int p   = blockIdx.x * NP_BLK + lp;
    const int br  = p / T_OUT;
    const int t   = p - br * T_OUT;

    // ---- Phase 1: taps in registers, compile-time segment emission ----
    float lin[K_TAPS];
    const float* xb = X + br * N_TIME + t + BASE_OFF;
    #pragma unroll
    for (int k = 0; k < K_TAPS; ++k) lin[k] = xb[SKIP * k];

    float* o = s_feat + lp * NF;

    #pragma unroll
    for (int Q = 0; Q < NSEG; ++Q) {
        if (q == Q) {
            const int lo = SEG_LO[Q];
            const int hi = SEG_LO[Q + 1];
            if (Q == 0) {
                o[0] = 1.0f;
                #pragma unroll
                for (int k = 0; k < K_TAPS; ++k) o[1 + k] = lin[k];
            }
            int m = 11;                             // compile-time after unroll
            #pragma unroll
            for (int a = 0; a < K_TAPS; ++a) {
                #pragma unroll
                for (int b = a; b < K_TAPS; ++b) {
                    const float pab = lin[a] * lin[b];
                    #pragma unroll
                    for (int c = b; c < K_TAPS; ++c) {
                        if (m >= lo && m < hi) o[m] = pab * lin[c];
                        ++m;
                    }
                }
            }
        }
    }
    __syncthreads();

    // ---- Phase 2: coalesced float4 copy shared -> global, extra ILP ----
    const float4* s4 = reinterpret_cast<const float4*>(s_feat);
    float4*       g4 = reinterpret_cast<float4*>(out) + blockIdx.x * V4_BLK;
    #pragma unroll 3
    for (int i = tid; i < V4_BLK; i += NTHREADS) {
        g4[i] = s4[i];
    }
}

extern "C" void kernel_launch(void* const* d_in, const int* in_sizes, int n_in,
                              void* d_out, int out_size) {
    const float* X   = (const float*)d_in[0];
    float*       out = (float*)d_out;
    (void)in_sizes; (void)n_in; (void)out_size;

    static bool configured = false;
    if (!configured) {
        // Lift the default shared-memory carveout so 7 CTAs/SM fit.
        cudaFuncSetAttribute(nvar_kernel,
                             cudaFuncAttributePreferredSharedMemoryCarveout, 100);
        cudaFuncSetAttribute(nvar_kernel,
                             cudaFuncAttributeMaxDynamicSharedMemorySize, SMEM_B);
        configured = true;
    }
    nvar_kernel<<<GRID, NTHREADS, SMEM_B>>>(X, out);
}

// round 15
// speedup vs baseline: 1.1621x; 1.1621x over previous
#include <cuda_runtime.h>

// NVAR feature expansion.  X: (8,4,4096) f32 -> out: (8,4,3996,231) f32
//   out[p, 0]      = 1
//   out[p, 1+k]    = lin[k] = X[br, t + 82 + 2k]
//   out[p, 11+m]   = lin[a]*lin[b]*lin[c], lex triples a<=b<=c over 0..9
//
// R12: same structure as the best kernel (32 pts / 128 thr CTA, compile-time
// monomial segments into smem, float4 copy out) but stores use st.global.cs
// (evict-first streaming): the 118MB output is written once and never re-read,
// so marking lines evict-first starts DRAM drain earlier and stops the output
// from thrashing all of L2 each graph iteration. Everything else unchanged —
// five prior designs pinned at 6.3 TB/s store-path ceiling; this targets the
// steady-state writeback residual.

constexpr int K_TAPS   = 10;
constexpr int NF       = 231;
constexpr int N_TIME   = 4096;
constexpr int T_OUT    = 3996;
constexpr int BASE_OFF = 82;           // TRANSIENTS - (K-1)*SKIP
constexpr int SKIP     = 2;

constexpr int NP_BLK   = 32;                        // points per CTA
constexpr int NTHREADS = 128;
constexpr int NSEG     = 4;
constexpr int FL_BLK   = NP_BLK * NF;               // 7392 floats (div by 4)
constexpr int V4_BLK   = FL_BLK / 4;                // 1848 float4
constexpr int GRID     = (8 * 4 * T_OUT) / NP_BLK;  // 3996 exactly
constexpr int SMEM_B   = FL_BLK * 4;                // 29568 bytes

__device__ constexpr int SEG_LO[NSEG + 1] = {0, 58, 116, 174, 231};

__device__ __forceinline__ void stg_cs_v4(float4* gptr, float4 v) {
    asm volatile("st.global.cs.v4.f32 [%0], {%1, %2, %3, %4};"
                 :: "l"(gptr), "f"(v.x), "f"(v.y), "f"(v.z), "f"(v.w)
                 : "memory");
}

__global__ __launch_bounds__(NTHREADS) void nvar_kernel(const float* __restrict__ X,
                                                        float* __restrict__ out) {
    extern __shared__ __align__(16) float s_feat[];  // point-major, stride NF

    const int tid = threadIdx.x;
    const int q   = tid >> 5;                       // warp = feature segment
    const int lp  = tid & 31;                       // lane = local point
    const int p   = blockIdx.x * NP_BLK + lp;
    const int br  = p / T_OUT;
    const int t   = p - br * T_OUT;

    // ---- Phase 1: taps in registers, compile-time segment emission ----
    float lin[K_TAPS];
    const float* xb = X + br * N_TIME + t + BASE_OFF;
    #pragma unroll
    for (int k = 0; k < K_TAPS; ++k) lin[k] = xb[SKIP * k];

    float* o = s_feat + lp * NF;

    #pragma unroll
    for (int Q = 0; Q < NSEG; ++Q) {
        if (q == Q) {
            const int lo = SEG_LO[Q];
            const int hi = SEG_LO[Q + 1];
            if (Q == 0) {
                o[0] = 1.0f;
                #pragma unroll
                for (int k = 0; k < K_TAPS; ++k) o[1 + k] = lin[k];
            }
            int m = 11;                             // compile-time after unroll
            #pragma unroll
            for (int a = 0; a < K_TAPS; ++a) {
                #pragma unroll
                for (int b = a; b < K_TAPS; ++b) {
                    const float pab = lin[a] * lin[b];
                    #pragma unroll
                    for (int c = b; c < K_TAPS; ++c) {
                        if (m >= lo && m < hi) o[m] = pab * lin[c];
                        ++m;
                    }
                }
            }
        }
    }
    __syncthreads();

    // ---- Phase 2: coalesced float4 streaming copy shared -> global ----
    const float4* s4 = reinterpret_cast<const float4*>(s_feat);
    float4*       g4 = reinterpret_cast<float4*>(out) + blockIdx.x * V4_BLK;
    for (int i = tid; i < V4_BLK; i += NTHREADS) {
        stg_cs_v4(g4 + i, s4[i]);
    }
}

extern "C" void kernel_launch(void* const* d_in, const int* in_sizes, int n_in,
                              void* d_out, int out_size) {
    const float* X   = (const float*)d_in[0];
    float*       out = (float*)d_out;
    (void)in_sizes; (void)n_in; (void)out_size;

    static bool configured = false;
    if (!configured) {
        cudaFuncSetAttribute(nvar_kernel,
                             cudaFuncAttributePreferredSharedMemoryCarveout, 100);
        cudaFuncSetAttribute(nvar_kernel,
                             cudaFuncAttributeMaxDynamicSharedMemorySize, SMEM_B);
        configured = true;
    }
    nvar_kernel<<<GRID, NTHREADS, SMEM_B>>>(X, out);
}